// round 3
// baseline (speedup 1.0000x reference)
#include <cuda_runtime.h>
#include <math.h>

#define NN 100000
#define NE 1600000
#define NF 500
#define NH 128
#define NC 40
#define SCAN_B 512
#define NBLK ((NN + SCAN_B - 1) / SCAN_B)   // 196

// ---------------- static device scratch (no allocs allowed) ----------------
__device__ float g_S[NN * NH];     // support = h @ W  (also used 40-wide for layer 4)
__device__ float g_H[NN * NH];     // hidden ping
__device__ float g_H2[NN * NH];    // hidden pong
__device__ float g_A4[NN * NC];    // layer-4 aggregate (pre log_softmax)
__device__ int   g_deg[NN];
__device__ int   g_cur[NN];
__device__ int   g_rp[NN + 1];     // CSR row pointers
__device__ int   g_cs[NE];         // CSR col (source node) per edge
__device__ float g_ws[NE];         // CSR edge weight
__device__ int   g_bsum[NBLK];

// ---------------- CSR construction ----------------
__global__ void k_zero() {
    int i = blockIdx.x * blockDim.x + threadIdx.x;
    if (i < NN) { g_deg[i] = 0; g_cur[i] = 0; }
}

__global__ void k_count(const int* __restrict__ row) {
    int e = blockIdx.x * blockDim.x + threadIdx.x;
    if (e < NE) atomicAdd(&g_deg[row[e]], 1);
}

__global__ void k_scan1() {
    __shared__ int s[SCAN_B];
    int i = blockIdx.x * SCAN_B + threadIdx.x;
    int v = (i < NN) ? g_deg[i] : 0;
    s[threadIdx.x] = v;
    __syncthreads();
    for (int off = 1; off < SCAN_B; off <<= 1) {
        int t = (threadIdx.x >= off) ? s[threadIdx.x - off] : 0;
        __syncthreads();
        s[threadIdx.x] += t;
        __syncthreads();
    }
    if (i < NN) g_rp[i] = s[threadIdx.x];             // block-local inclusive
    if (threadIdx.x == SCAN_B - 1) g_bsum[blockIdx.x] = s[SCAN_B - 1];
}

__global__ void k_scan2() {
    __shared__ int s[256];
    int v = (threadIdx.x < NBLK) ? g_bsum[threadIdx.x] : 0;
    s[threadIdx.x] = v;
    __syncthreads();
    for (int off = 1; off < 256; off <<= 1) {
        int t = (threadIdx.x >= off) ? s[threadIdx.x - off] : 0;
        __syncthreads();
        s[threadIdx.x] += t;
        __syncthreads();
    }
    if (threadIdx.x < NBLK) g_bsum[threadIdx.x] = s[threadIdx.x] - v;  // exclusive
}

__global__ void k_scan3() {
    int i = blockIdx.x * SCAN_B + threadIdx.x;
    if (i < NN) g_rp[i] = g_rp[i] - g_deg[i] + g_bsum[blockIdx.x];     // global exclusive
    if (i == 0) g_rp[NN] = NE;
}

__global__ void k_scatter(const int* __restrict__ row, const int* __restrict__ col,
                          const float* __restrict__ w) {
    int e = blockIdx.x * blockDim.x + threadIdx.x;
    if (e < NE) {
        int r = row[e];
        int pos = g_rp[r] + atomicAdd(&g_cur[r], 1);
        g_cs[pos] = col[e];
        g_ws[pos] = w[e];
    }
}

// ---------------- fp32 SIMT tiled GEMM: C[M,N] = A[M,K] @ B[K,N] ----------------
// BM=128, BN=128, BK=8, 256 threads, 8x8 per thread.
__global__ __launch_bounds__(256) void k_gemm(const float* __restrict__ A,
                                              const float* __restrict__ B,
                                              float* __restrict__ C,
                                              int M, int K, int N) {
    __shared__ float As[8][128];
    __shared__ float Bs[8][128];
    const int m0  = blockIdx.x * 128;
    const int tid = threadIdx.x;
    const int tm = tid >> 4;          // 0..15
    const int tn = tid & 15;          // 0..15

    const int la_m = tid >> 1;        // 0..127
    const int la_k = (tid & 1) * 4;   // 0 or 4
    const int lb_k = tid >> 5;        // 0..7
    const int lb_n = (tid & 31) * 4;  // 0..124

    float acc[8][8];
#pragma unroll
    for (int i = 0; i < 8; i++)
#pragma unroll
        for (int j = 0; j < 8; j++) acc[i][j] = 0.f;

    for (int k0 = 0; k0 < K; k0 += 8) {
        // A tile (transposed into smem), zero-pad OOB
        {
            int m = m0 + la_m;
#pragma unroll
            for (int i = 0; i < 4; i++) {
                int k = k0 + la_k + i;
                As[la_k + i][la_m] = (m < M && k < K) ? A[(size_t)m * K + k] : 0.f;
            }
        }
        // B tile, zero-pad OOB
        {
            int k = k0 + lb_k;
#pragma unroll
            for (int i = 0; i < 4; i++) {
                int n = lb_n + i;
                Bs[lb_k][n] = (k < K && n < N) ? B[(size_t)k * N + n] : 0.f;
            }
        }
        __syncthreads();
#pragma unroll
        for (int kk = 0; kk < 8; kk++) {
            float a[8], b[8];
            float4 a0 = *(const float4*)&As[kk][tm * 8];
            float4 a1 = *(const float4*)&As[kk][tm * 8 + 4];
            float4 b0 = *(const float4*)&Bs[kk][tn * 8];
            float4 b1 = *(const float4*)&Bs[kk][tn * 8 + 4];
            a[0]=a0.x; a[1]=a0.y; a[2]=a0.z; a[3]=a0.w;
            a[4]=a1.x; a[5]=a1.y; a[6]=a1.z; a[7]=a1.w;
            b[0]=b0.x; b[1]=b0.y; b[2]=b0.z; b[3]=b0.w;
            b[4]=b1.x; b[5]=b1.y; b[6]=b1.z; b[7]=b1.w;
#pragma unroll
            for (int i = 0; i < 8; i++)
#pragma unroll
                for (int j = 0; j < 8; j++) acc[i][j] += a[i] * b[j];
        }
        __syncthreads();
    }
#pragma unroll
    for (int i = 0; i < 8; i++) {
        int m = m0 + tm * 8 + i;
        if (m >= M) continue;
#pragma unroll
        for (int j = 0; j < 8; j++) {
            int n = tn * 8 + j;
            if (n < N) C[(size_t)m * N + n] = acc[i][j];
        }
    }
}

// ---------------- CSR SpMM + bias (+relu): H[r,:] = sum_e w[e]*S[col[e],:] + b ----------------
// One warp per row; each lane owns 4 contiguous features (float4).
__global__ __launch_bounds__(256) void k_spmm(const float* __restrict__ S,
                                              float* __restrict__ H,
                                              const float* __restrict__ bias,
                                              int F, int do_relu) {
    int wid  = (blockIdx.x * 256 + threadIdx.x) >> 5;
    if (wid >= NN) return;
    int lane = threadIdx.x & 31;
    int f    = lane * 4;
    if (f >= F) return;
    int fq = f >> 2, Fq = F >> 2;

    int beg = g_rp[wid], end = g_rp[wid + 1];
    const float4* Sv = (const float4*)S;
    float4 acc = make_float4(0.f, 0.f, 0.f, 0.f);
    for (int e = beg; e < end; e++) {
        int   c = g_cs[e];            // broadcast within warp (same address)
        float w = g_ws[e];
        float4 v = Sv[(size_t)c * Fq + fq];
        acc.x += w * v.x; acc.y += w * v.y; acc.z += w * v.z; acc.w += w * v.w;
    }
    float4 b = ((const float4*)bias)[fq];
    acc.x += b.x; acc.y += b.y; acc.z += b.z; acc.w += b.w;
    if (do_relu) {
        acc.x = fmaxf(acc.x, 0.f); acc.y = fmaxf(acc.y, 0.f);
        acc.z = fmaxf(acc.z, 0.f); acc.w = fmaxf(acc.w, 0.f);
    }
    ((float4*)H)[(size_t)wid * Fq + fq] = acc;
}

// ---------------- log_softmax over 40 classes, one warp per row ----------------
__global__ __launch_bounds__(256) void k_lsm(float* __restrict__ out) {
    int wid = (blockIdx.x * 256 + threadIdx.x) >> 5;
    if (wid >= NN) return;
    int lane = threadIdx.x & 31;
    const float* a = g_A4 + (size_t)wid * NC;
    float v0 = a[lane];                                     // lane < 32 < 40: always valid
    float v1 = (lane + 32 < NC) ? a[lane + 32] : -1e30f;
    float m = fmaxf(v0, v1);
#pragma unroll
    for (int o = 16; o; o >>= 1) m = fmaxf(m, __shfl_xor_sync(0xffffffffu, m, o));
    float s = expf(v0 - m) + ((lane + 32 < NC) ? expf(v1 - m) : 0.f);
#pragma unroll
    for (int o = 16; o; o >>= 1) s += __shfl_xor_sync(0xffffffffu, s, o);
    float l = m + logf(s);
    out[(size_t)wid * NC + lane] = v0 - l;
    if (lane + 32 < NC) out[(size_t)wid * NC + lane + 32] = v1 - l;
}

// ---------------- launch ----------------
extern "C" void kernel_launch(void* const* d_in, const int* in_sizes, int n_in,
                              void* d_out, int out_size) {
    const float* x  = (const float*)d_in[0];
    const int*   row = (const int*)d_in[1];
    const int*   col = (const int*)d_in[2];
    const float* ew  = (const float*)d_in[3];
    const float* W1 = (const float*)d_in[4];  const float* b1 = (const float*)d_in[5];
    const float* W2 = (const float*)d_in[6];  const float* b2 = (const float*)d_in[7];
    const float* W3 = (const float*)d_in[8];  const float* b3 = (const float*)d_in[9];
    const float* W4 = (const float*)d_in[10]; const float* b4 = (const float*)d_in[11];
    float* out = (float*)d_out;

    void *pS, *pH, *pH2, *pA4;
    cudaGetSymbolAddress(&pS,  g_S);
    cudaGetSymbolAddress(&pH,  g_H);
    cudaGetSymbolAddress(&pH2, g_H2);
    cudaGetSymbolAddress(&pA4, g_A4);
    float* S  = (float*)pS;
    float* H  = (float*)pH;
    float* H2 = (float*)pH2;
    float* A4 = (float*)pA4;

    const int EB = (NE + 255) / 256;
    const int GM = (NN + 127) / 128;     // 782 GEMM row tiles
    const int SB = (NN + 7) / 8;         // 12500 blocks, 8 warps/block, warp per row

    // CSR build (reused by all 4 layers)
    k_zero<<<(NN + 255) / 256, 256>>>();
    k_count<<<EB, 256>>>(row);
    k_scan1<<<NBLK, SCAN_B>>>();
    k_scan2<<<1, 256>>>();
    k_scan3<<<NBLK, SCAN_B>>>();
    k_scatter<<<EB, 256>>>(row, col, ew);

    // layer 1: relu(spmm(x @ W1) + b1)
    k_gemm<<<GM, 256>>>(x, W1, S, NN, NF, NH);
    k_spmm<<<SB, 256>>>(S, H, b1, NH, 1);
    // layer 2
    k_gemm<<<GM, 256>>>(H, W2, S, NN, NH, NH);
    k_spmm<<<SB, 256>>>(S, H2, b2, NH, 1);
    // layer 3
    k_gemm<<<GM, 256>>>(H2, W3, S, NN, NH, NH);
    k_spmm<<<SB, 256>>>(S, H, b3, NH, 1);
    // layer 4 (no relu) + log_softmax
    k_gemm<<<GM, 256>>>(H, W4, S, NN, NH, NC);
    k_spmm<<<SB, 256>>>(S, A4, b4, NC, 0);
    k_lsm<<<SB, 256>>>(out);
}

// round 6
// speedup vs baseline: 1.2111x; 1.2111x over previous
#include <cuda_runtime.h>
#include <cuda_bf16.h>
#include <cstdint>
#include <cstring>
#include <math.h>

#define NN 100000
#define NE 1600000
#define NF 500
#define NH 128
#define NC 40
#define SCAN_B 512
#define NBLK ((NN + SCAN_B - 1) / SCAN_B)   // 196

// ---------------- static device scratch (no allocs allowed) ----------------
__device__ float g_S[NN * NH];     // support = h @ W
__device__ float g_H[NN * NH];     // hidden ping
__device__ float g_H2[NN * NH];    // hidden pong
__device__ float g_A4[NN * NC];    // layer-4 aggregate (pre log_softmax)
__device__ int   g_deg[NN];
__device__ int   g_cur[NN];
__device__ int   g_rp[NN + 1];     // CSR row pointers
__device__ int   g_cs[NE];         // CSR col (source node) per edge
__device__ float g_ws[NE];         // CSR edge weight
__device__ int   g_bsum[NBLK];

// ---------------- CSR construction ----------------
__global__ void k_zero() {
    int i = blockIdx.x * blockDim.x + threadIdx.x;
    if (i < NN) { g_deg[i] = 0; g_cur[i] = 0; }
}
__global__ void k_count(const int* __restrict__ row) {
    int e = blockIdx.x * blockDim.x + threadIdx.x;
    if (e < NE) atomicAdd(&g_deg[row[e]], 1);
}
__global__ void k_scan1() {
    __shared__ int s[SCAN_B];
    int i = blockIdx.x * SCAN_B + threadIdx.x;
    int v = (i < NN) ? g_deg[i] : 0;
    s[threadIdx.x] = v;
    __syncthreads();
    for (int off = 1; off < SCAN_B; off <<= 1) {
        int t = (threadIdx.x >= off) ? s[threadIdx.x - off] : 0;
        __syncthreads();
        s[threadIdx.x] += t;
        __syncthreads();
    }
    if (i < NN) g_rp[i] = s[threadIdx.x];
    if (threadIdx.x == SCAN_B - 1) g_bsum[blockIdx.x] = s[SCAN_B - 1];
}
__global__ void k_scan2() {
    __shared__ int s[256];
    int v = (threadIdx.x < NBLK) ? g_bsum[threadIdx.x] : 0;
    s[threadIdx.x] = v;
    __syncthreads();
    for (int off = 1; off < 256; off <<= 1) {
        int t = (threadIdx.x >= off) ? s[threadIdx.x - off] : 0;
        __syncthreads();
        s[threadIdx.x] += t;
        __syncthreads();
    }
    if (threadIdx.x < NBLK) g_bsum[threadIdx.x] = s[threadIdx.x] - v;
}
__global__ void k_scan3() {
    int i = blockIdx.x * SCAN_B + threadIdx.x;
    if (i < NN) g_rp[i] = g_rp[i] - g_deg[i] + g_bsum[blockIdx.x];
    if (i == 0) g_rp[NN] = NE;
}
__global__ void k_scatter(const int* __restrict__ row, const int* __restrict__ col,
                          const float* __restrict__ w) {
    int e = blockIdx.x * blockDim.x + threadIdx.x;
    if (e < NE) {
        int r = row[e];
        int pos = g_rp[r] + atomicAdd(&g_cur[r], 1);
        g_cs[pos] = col[e];
        g_ws[pos] = w[e];
    }
}

// ---------------- bf16-split tensor-core GEMM (mma.sync, works on compute_103) ----
// C[M,128] = A[M,K] @ W[K,128], fp32 in/out.
// A,B split hi/lo bf16; acc += Ah*Bh + Ah*Bl + Al*Bh  (~2^-17 effective precision).
// CTA: 128x128 tile, BK=32, 256 threads = 8 warps (4 m x 2 n), warp tile 32x64.
#define LDT 40   // padded bf16 row length (80 B rows -> conflict-free ldmatrix)

__device__ __forceinline__ uint32_t smem_u32(const void* p) {
    uint32_t a;
    asm("{ .reg .u64 t; cvta.to.shared.u64 t, %1; cvt.u32.u64 %0, t; }" : "=r"(a) : "l"(p));
    return a;
}
__device__ __forceinline__ uint32_t pack2bf(float x, float y) {
    __nv_bfloat162 t = __floats2bfloat162_rn(x, y);
    uint32_t u; memcpy(&u, &t, 4); return u;
}
#define LDMX4(r0, r1, r2, r3, a) \
    asm volatile("ldmatrix.sync.aligned.m8n8.x4.shared.b16 {%0,%1,%2,%3}, [%4];" \
                 : "=r"(r0), "=r"(r1), "=r"(r2), "=r"(r3) : "r"(a))
#define MMA16816(d, a, b0v, b1v) \
    asm volatile("mma.sync.aligned.m16n8k16.row.col.f32.bf16.bf16.f32 " \
                 "{%0,%1,%2,%3}, {%4,%5,%6,%7}, {%8,%9}, {%0,%1,%2,%3};" \
                 : "+f"((d)[0]), "+f"((d)[1]), "+f"((d)[2]), "+f"((d)[3]) \
                 : "r"((a)[0]), "r"((a)[1]), "r"((a)[2]), "r"((a)[3]), \
                   "r"(b0v), "r"(b1v))

__global__ __launch_bounds__(256) void k_gemm_mma(const float* __restrict__ A,
                                                  const float* __restrict__ W,
                                                  float* __restrict__ C,
                                                  int M, int K) {
    __shared__ __align__(16) __nv_bfloat16 sAh[128 * LDT];
    __shared__ __align__(16) __nv_bfloat16 sAl[128 * LDT];
    __shared__ __align__(16) __nv_bfloat16 sBh[128 * LDT];
    __shared__ __align__(16) __nv_bfloat16 sBl[128 * LDT];

    const int tid  = threadIdx.x;
    const int wid  = tid >> 5, lane = tid & 31;
    const int m0   = blockIdx.x * 128;
    const int wm   = (wid & 3) * 32;    // warp row base
    const int wn   = (wid >> 2) * 64;   // warp col base

    // ldmatrix lane address components
    const int lr  = lane & 7;           // row within 8x8
    const int grp = lane >> 3;          // which 8x8 matrix
    // A tile (row-major): grp0 rows+0/k+0, grp1 rows+8/k+0, grp2 rows+0/k+8, grp3 rows+8/k+8
    const int aRow = (grp & 1) * 8 + lr;
    const int aCol = (grp >> 1) * 8;
    // B tile (Bt rows = n, cols = k): grp0 n+0/k+0, grp1 n+0/k+8, grp2 n+8/k+0, grp3 n+8/k+8
    const int bRow = (grp >> 1) * 8 + lr;
    const int bCol = (grp & 1) * 8;

    const uint32_t uAh = smem_u32(sAh), uAl = smem_u32(sAl);
    const uint32_t uBh = smem_u32(sBh), uBl = smem_u32(sBl);

    float acc[2][8][4];
#pragma unroll
    for (int i = 0; i < 2; i++)
#pragma unroll
        for (int j = 0; j < 8; j++)
#pragma unroll
            for (int q = 0; q < 4; q++) acc[i][j][q] = 0.f;

    const int nchunk = (K + 31) / 32;
    for (int c = 0; c < nchunk; c++) {
        const int k0 = c * 32;

        // ---- A fill: 128 rows x 32 k, hi/lo split
        {
            int q  = tid & 7;          // k-quad
            int r0 = tid >> 3;         // 0..31
            int kk = q * 4, k = k0 + kk;
#pragma unroll
            for (int rr = 0; rr < 128; rr += 32) {
                int r = rr + r0, m = m0 + r;
                float4 v = make_float4(0.f, 0.f, 0.f, 0.f);
                if (m < M) {
                    if (k + 3 < K) v = *(const float4*)(A + (size_t)m * K + k);
                    else {
                        const float* ap = A + (size_t)m * K;
                        if (k     < K) v.x = ap[k];
                        if (k + 1 < K) v.y = ap[k + 1];
                        if (k + 2 < K) v.z = ap[k + 2];
                        if (k + 3 < K) v.w = ap[k + 3];
                    }
                }
                __nv_bfloat162 h01 = __floats2bfloat162_rn(v.x, v.y);
                __nv_bfloat162 h23 = __floats2bfloat162_rn(v.z, v.w);
                float lx = v.x - __bfloat162float(h01.x);
                float ly = v.y - __bfloat162float(h01.y);
                float lz = v.z - __bfloat162float(h23.x);
                float lw = v.w - __bfloat162float(h23.y);
                uint32_t uh01, uh23;
                memcpy(&uh01, &h01, 4); memcpy(&uh23, &h23, 4);
                *(uint2*)&sAh[r * LDT + kk] = make_uint2(uh01, uh23);
                *(uint2*)&sAl[r * LDT + kk] = make_uint2(pack2bf(lx, ly), pack2bf(lz, lw));
            }
        }
        // ---- B fill (transposed): Bt[n][kk] = W[k0+kk][n]
        {
            int n  = tid & 127;
            int kh = tid >> 7;         // 0..1
#pragma unroll
            for (int kk0 = 0; kk0 < 32; kk0 += 2) {
                int kk = kk0 + kh, k = k0 + kk;
                float w = (k < K) ? W[(size_t)k * 128 + n] : 0.f;
                __nv_bfloat16 h = __float2bfloat16(w);
                float l = w - __bfloat162float(h);
                sBh[n * LDT + kk] = h;
                sBl[n * LDT + kk] = __float2bfloat16(l);
            }
        }
        __syncthreads();

        // ---- compute: 2 k-steps of 16
#pragma unroll
        for (int ks = 0; ks < 2; ks++) {
            const int kb = ks * 16;
            uint32_t ah[2][4], al[2][4];
#pragma unroll
            for (int mt = 0; mt < 2; mt++) {
                uint32_t off = (uint32_t)((wm + mt * 16 + aRow) * LDT + kb + aCol) * 2;
                LDMX4(ah[mt][0], ah[mt][1], ah[mt][2], ah[mt][3], uAh + off);
                LDMX4(al[mt][0], al[mt][1], al[mt][2], al[mt][3], uAl + off);
            }
#pragma unroll
            for (int p = 0; p < 4; p++) {           // pairs of n-tiles (16 cols)
                uint32_t off = (uint32_t)((wn + p * 16 + bRow) * LDT + kb + bCol) * 2;
                uint32_t bh[4], bl[4];
                LDMX4(bh[0], bh[1], bh[2], bh[3], uBh + off);
                LDMX4(bl[0], bl[1], bl[2], bl[3], uBl + off);
#pragma unroll
                for (int mt = 0; mt < 2; mt++) {
                    MMA16816(acc[mt][2 * p],     ah[mt], bh[0], bh[1]);
                    MMA16816(acc[mt][2 * p],     ah[mt], bl[0], bl[1]);
                    MMA16816(acc[mt][2 * p],     al[mt], bh[0], bh[1]);
                    MMA16816(acc[mt][2 * p + 1], ah[mt], bh[2], bh[3]);
                    MMA16816(acc[mt][2 * p + 1], ah[mt], bl[2], bl[3]);
                    MMA16816(acc[mt][2 * p + 1], al[mt], bh[2], bh[3]);
                }
            }
        }
        __syncthreads();
    }

    // ---- epilogue: fragment rows lane/4 (+8), cols 2*(lane%4)
    const int fr = lane >> 2, fc = (lane & 3) * 2;
#pragma unroll
    for (int mt = 0; mt < 2; mt++) {
        int r0 = m0 + wm + mt * 16 + fr;
#pragma unroll
        for (int nt = 0; nt < 8; nt++) {
            int cbase = wn + nt * 8 + fc;
            if (r0 < M)
                *(float2*)(C + (size_t)r0 * 128 + cbase) =
                    make_float2(acc[mt][nt][0], acc[mt][nt][1]);
            if (r0 + 8 < M)
                *(float2*)(C + (size_t)(r0 + 8) * 128 + cbase) =
                    make_float2(acc[mt][nt][2], acc[mt][nt][3]);
        }
    }
}

// ---------------- fp32 SIMT tiled GEMM (layer 4 only, N=40) ----------------
__global__ __launch_bounds__(256) void k_gemm(const float* __restrict__ A,
                                              const float* __restrict__ B,
                                              float* __restrict__ C,
                                              int M, int K, int N) {
    __shared__ float As[8][128];
    __shared__ float Bs[8][128];
    const int m0  = blockIdx.x * 128;
    const int tid = threadIdx.x;
    const int tm = tid >> 4;
    const int tn = tid & 15;
    const int la_m = tid >> 1;
    const int la_k = (tid & 1) * 4;
    const int lb_k = tid >> 5;
    const int lb_n = (tid & 31) * 4;

    float acc[8][8];
#pragma unroll
    for (int i = 0; i < 8; i++)
#pragma unroll
        for (int j = 0; j < 8; j++) acc[i][j] = 0.f;

    for (int k0 = 0; k0 < K; k0 += 8) {
        {
            int m = m0 + la_m;
#pragma unroll
            for (int i = 0; i < 4; i++) {
                int k = k0 + la_k + i;
                As[la_k + i][la_m] = (m < M && k < K) ? A[(size_t)m * K + k] : 0.f;
            }
        }
        {
            int k = k0 + lb_k;
#pragma unroll
            for (int i = 0; i < 4; i++) {
                int n = lb_n + i;
                Bs[lb_k][n] = (k < K && n < N) ? B[(size_t)k * N + n] : 0.f;
            }
        }
        __syncthreads();
#pragma unroll
        for (int kk = 0; kk < 8; kk++) {
            float a[8], b[8];
            float4 a0 = *(const float4*)&As[kk][tm * 8];
            float4 a1 = *(const float4*)&As[kk][tm * 8 + 4];
            float4 b0 = *(const float4*)&Bs[kk][tn * 8];
            float4 b1 = *(const float4*)&Bs[kk][tn * 8 + 4];
            a[0]=a0.x; a[1]=a0.y; a[2]=a0.z; a[3]=a0.w;
            a[4]=a1.x; a[5]=a1.y; a[6]=a1.z; a[7]=a1.w;
            b[0]=b0.x; b[1]=b0.y; b[2]=b0.z; b[3]=b0.w;
            b[4]=b1.x; b[5]=b1.y; b[6]=b1.z; b[7]=b1.w;
#pragma unroll
            for (int i = 0; i < 8; i++)
#pragma unroll
                for (int j = 0; j < 8; j++) acc[i][j] += a[i] * b[j];
        }
        __syncthreads();
    }
#pragma unroll
    for (int i = 0; i < 8; i++) {
        int m = m0 + tm * 8 + i;
        if (m >= M) continue;
#pragma unroll
        for (int j = 0; j < 8; j++) {
            int n = tn * 8 + j;
            if (n < N) C[(size_t)m * N + n] = acc[i][j];
        }
    }
}

// ---------------- CSR SpMM + bias (+relu) ----------------
__global__ __launch_bounds__(256) void k_spmm(const float* __restrict__ S,
                                              float* __restrict__ H,
                                              const float* __restrict__ bias,
                                              int F, int do_relu) {
    int wid  = (blockIdx.x * 256 + threadIdx.x) >> 5;
    if (wid >= NN) return;
    int lane = threadIdx.x & 31;
    int f    = lane * 4;
    if (f >= F) return;
    int fq = f >> 2, Fq = F >> 2;

    int beg = g_rp[wid], end = g_rp[wid + 1];
    const float4* Sv = (const float4*)S;
    float4 acc = make_float4(0.f, 0.f, 0.f, 0.f);
    for (int e = beg; e < end; e++) {
        int   c = g_cs[e];
        float w = g_ws[e];
        float4 v = Sv[(size_t)c * Fq + fq];
        acc.x += w * v.x; acc.y += w * v.y; acc.z += w * v.z; acc.w += w * v.w;
    }
    float4 b = ((const float4*)bias)[fq];
    acc.x += b.x; acc.y += b.y; acc.z += b.z; acc.w += b.w;
    if (do_relu) {
        acc.x = fmaxf(acc.x, 0.f); acc.y = fmaxf(acc.y, 0.f);
        acc.z = fmaxf(acc.z, 0.f); acc.w = fmaxf(acc.w, 0.f);
    }
    ((float4*)H)[(size_t)wid * Fq + fq] = acc;
}

// ---------------- log_softmax over 40 classes ----------------
__global__ __launch_bounds__(256) void k_lsm(float* __restrict__ out) {
    int wid = (blockIdx.x * 256 + threadIdx.x) >> 5;
    if (wid >= NN) return;
    int lane = threadIdx.x & 31;
    const float* a = g_A4 + (size_t)wid * NC;
    float v0 = a[lane];
    float v1 = (lane + 32 < NC) ? a[lane + 32] : -1e30f;
    float m = fmaxf(v0, v1);
#pragma unroll
    for (int o = 16; o; o >>= 1) m = fmaxf(m, __shfl_xor_sync(0xffffffffu, m, o));
    float s = expf(v0 - m) + ((lane + 32 < NC) ? expf(v1 - m) : 0.f);
#pragma unroll
    for (int o = 16; o; o >>= 1) s += __shfl_xor_sync(0xffffffffu, s, o);
    float l = m + logf(s);
    out[(size_t)wid * NC + lane] = v0 - l;
    if (lane + 32 < NC) out[(size_t)wid * NC + lane + 32] = v1 - l;
}

// ---------------- launch ----------------
extern "C" void kernel_launch(void* const* d_in, const int* in_sizes, int n_in,
                              void* d_out, int out_size) {
    const float* x  = (const float*)d_in[0];
    const int*   row = (const int*)d_in[1];
    const int*   col = (const int*)d_in[2];
    const float* ew  = (const float*)d_in[3];
    const float* W1 = (const float*)d_in[4];  const float* b1 = (const float*)d_in[5];
    const float* W2 = (const float*)d_in[6];  const float* b2 = (const float*)d_in[7];
    const float* W3 = (const float*)d_in[8];  const float* b3 = (const float*)d_in[9];
    const float* W4 = (const float*)d_in[10]; const float* b4 = (const float*)d_in[11];
    float* out = (float*)d_out;

    void *pS, *pH, *pH2, *pA4;
    cudaGetSymbolAddress(&pS,  g_S);
    cudaGetSymbolAddress(&pH,  g_H);
    cudaGetSymbolAddress(&pH2, g_H2);
    cudaGetSymbolAddress(&pA4, g_A4);
    float* S  = (float*)pS;
    float* H  = (float*)pH;
    float* H2 = (float*)pH2;
    float* A4 = (float*)pA4;

    const int EB = (NE + 255) / 256;
    const int GM = (NN + 127) / 128;     // 782 row tiles
    const int SB = (NN + 7) / 8;         // warp-per-row

    // CSR build (reused by all 4 layers)
    k_zero<<<(NN + 255) / 256, 256>>>();
    k_count<<<EB, 256>>>(row);
    k_scan1<<<NBLK, SCAN_B>>>();
    k_scan2<<<1, 256>>>();
    k_scan3<<<NBLK, SCAN_B>>>();
    k_scatter<<<EB, 256>>>(row, col, ew);

    // layer 1: relu(spmm(x @ W1) + b1)   — tensor-core GEMM (bf16 split)
    k_gemm_mma<<<GM, 256>>>(x, W1, S, NN, NF);
    k_spmm<<<SB, 256>>>(S, H, b1, NH, 1);
    // layer 2
    k_gemm_mma<<<GM, 256>>>(H, W2, S, NN, NH);
    k_spmm<<<SB, 256>>>(S, H2, b2, NH, 1);
    // layer 3
    k_gemm_mma<<<GM, 256>>>(H2, W3, S, NN, NH);
    k_spmm<<<SB, 256>>>(S, H, b3, NH, 1);
    // layer 4 (N=40, SIMT) + log_softmax
    k_gemm<<<GM, 256>>>(H, W4, S, NN, NH, NC);
    k_spmm<<<SB, 256>>>(S, A4, b4, NC, 0);
    k_lsm<<<SB, 256>>>(out);
}

// round 7
// speedup vs baseline: 2.1493x; 1.7747x over previous
#include <cuda_runtime.h>
#include <cuda_bf16.h>
#include <cstdint>
#include <cstring>
#include <math.h>

#define NN 100000
#define NE 1600000
#define NF 500
#define NH 128
#define NC 40
#define SCAN_B 512
#define NBLK ((NN + SCAN_B - 1) / SCAN_B)   // 196

// ---------------- static device scratch (no allocs allowed) ----------------
__device__ float g_S[NN * NH];     // support = h @ W
__device__ float g_H[NN * NH];     // hidden ping
__device__ float g_H2[NN * NH];    // hidden pong
__device__ float g_A4[NN * NC];    // layer-4 aggregate (pre log_softmax)
__device__ float g_W4p[128 * 128]; // W4 zero-padded to 128 cols
__device__ int   g_deg[NN];
__device__ int   g_cur[NN];
__device__ int   g_rp[NN + 1];     // CSR row pointers
__device__ int   g_cs[NE];         // CSR col (source node) per edge
__device__ float g_ws[NE];         // CSR edge weight
__device__ int   g_bsum[NBLK];

// ---------------- CSR construction ----------------
__global__ void k_zero() {
    int i = blockIdx.x * blockDim.x + threadIdx.x;
    if (i < NN) { g_deg[i] = 0; g_cur[i] = 0; }
}
__global__ void k_count(const int* __restrict__ row) {
    int e = blockIdx.x * blockDim.x + threadIdx.x;
    if (e < NE) atomicAdd(&g_deg[row[e]], 1);
}
__global__ void k_scan1() {
    __shared__ int s[SCAN_B];
    int i = blockIdx.x * SCAN_B + threadIdx.x;
    int v = (i < NN) ? g_deg[i] : 0;
    s[threadIdx.x] = v;
    __syncthreads();
    for (int off = 1; off < SCAN_B; off <<= 1) {
        int t = (threadIdx.x >= off) ? s[threadIdx.x - off] : 0;
        __syncthreads();
        s[threadIdx.x] += t;
        __syncthreads();
    }
    if (i < NN) g_rp[i] = s[threadIdx.x];
    if (threadIdx.x == SCAN_B - 1) g_bsum[blockIdx.x] = s[SCAN_B - 1];
}
__global__ void k_scan2() {
    __shared__ int s[256];
    int v = (threadIdx.x < NBLK) ? g_bsum[threadIdx.x] : 0;
    s[threadIdx.x] = v;
    __syncthreads();
    for (int off = 1; off < 256; off <<= 1) {
        int t = (threadIdx.x >= off) ? s[threadIdx.x - off] : 0;
        __syncthreads();
        s[threadIdx.x] += t;
        __syncthreads();
    }
    if (threadIdx.x < NBLK) g_bsum[threadIdx.x] = s[threadIdx.x] - v;
}
__global__ void k_scan3() {
    int i = blockIdx.x * SCAN_B + threadIdx.x;
    if (i < NN) g_rp[i] = g_rp[i] - g_deg[i] + g_bsum[blockIdx.x];
    if (i == 0) g_rp[NN] = NE;
}
__global__ void k_scatter(const int* __restrict__ row, const int* __restrict__ col,
                          const float* __restrict__ w) {
    int e = blockIdx.x * blockDim.x + threadIdx.x;
    if (e < NE) {
        int r = row[e];
        int pos = g_rp[r] + atomicAdd(&g_cur[r], 1);
        g_cs[pos] = col[e];
        g_ws[pos] = w[e];
    }
}
__global__ void k_padw4(const float* __restrict__ W4) {
    int i = blockIdx.x * blockDim.x + threadIdx.x;   // 128*128
    int k = i >> 7, n = i & 127;
    g_W4p[i] = (n < NC) ? W4[k * NC + n] : 0.f;
}

// ---------------- bf16-split tensor-core GEMM (mma.sync) ----------------
// C[M,128] = A[M,K] @ W[K,128], fp32 in/out.
// acc += Ah*Bh + Ah*Bl + Al*Bh  (~2^-17 effective precision).
// CTA: 128x128 tile, BK=32, 256 threads = 8 warps (4m x 2n), warp tile 32x64.
// A smem: [m][k] rows (LDT=40 pad). B smem: [k][n] rows (LDB=136 pad) + ldmatrix.trans.
// Software pipeline: prefetch chunk c+1 to registers while computing chunk c.
#define LDT 40
#define LDB 136

__device__ __forceinline__ uint32_t smem_u32(const void* p) {
    uint32_t a;
    asm("{ .reg .u64 t; cvta.to.shared.u64 t, %1; cvt.u32.u64 %0, t; }" : "=r"(a) : "l"(p));
    return a;
}
__device__ __forceinline__ uint32_t pack2bf(float x, float y) {
    __nv_bfloat162 t = __floats2bfloat162_rn(x, y);
    uint32_t u; memcpy(&u, &t, 4); return u;
}
#define LDMX4(r0, r1, r2, r3, a) \
    asm volatile("ldmatrix.sync.aligned.m8n8.x4.shared.b16 {%0,%1,%2,%3}, [%4];" \
                 : "=r"(r0), "=r"(r1), "=r"(r2), "=r"(r3) : "r"(a))
#define LDMX4T(r0, r1, r2, r3, a) \
    asm volatile("ldmatrix.sync.aligned.m8n8.x4.trans.shared.b16 {%0,%1,%2,%3}, [%4];" \
                 : "=r"(r0), "=r"(r1), "=r"(r2), "=r"(r3) : "r"(a))
#define MMA16816(d, a, b0v, b1v) \
    asm volatile("mma.sync.aligned.m16n8k16.row.col.f32.bf16.bf16.f32 " \
                 "{%0,%1,%2,%3}, {%4,%5,%6,%7}, {%8,%9}, {%0,%1,%2,%3};" \
                 : "+f"((d)[0]), "+f"((d)[1]), "+f"((d)[2]), "+f"((d)[3]) \
                 : "r"((a)[0]), "r"((a)[1]), "r"((a)[2]), "r"((a)[3]), \
                   "r"(b0v), "r"(b1v))

__global__ __launch_bounds__(256, 1) void k_gemm_mma(const float* __restrict__ A,
                                                     const float* __restrict__ W,
                                                     float* __restrict__ C,
                                                     int M, int K) {
    __shared__ __align__(16) __nv_bfloat16 sAh[128 * LDT];
    __shared__ __align__(16) __nv_bfloat16 sAl[128 * LDT];
    __shared__ __align__(16) __nv_bfloat16 sBh[32 * LDB];
    __shared__ __align__(16) __nv_bfloat16 sBl[32 * LDB];

    const int tid  = threadIdx.x;
    const int wid  = tid >> 5, lane = tid & 31;
    const int m0   = blockIdx.x * 128;
    const int wm   = (wid & 3) * 32;    // warp row base
    const int wn   = (wid >> 2) * 64;   // warp col base

    // ldmatrix lane address components
    const int lr  = lane & 7;
    const int grp = lane >> 3;
    const int aRow = (grp & 1) * 8 + lr;   // A: m offset
    const int aCol = (grp >> 1) * 8;       // A: k offset
    const int bK   = (grp & 1) * 8 + lr;   // B: k row (trans)
    const int bN   = (grp >> 1) * 8;       // B: n offset

    // fill index components
    const int fqA = (tid & 7) * 4;         // A k within chunk
    const int frA = tid >> 3;              // A row 0..31 (stride 32)
    const int fkB = tid >> 5;              // B k 0..7 (stride 8)
    const int fnB = (tid & 31) * 4;        // B n

    const uint32_t uAh = smem_u32(sAh), uAl = smem_u32(sAl);
    const uint32_t uBh = smem_u32(sBh), uBl = smem_u32(sBl);

    float acc[2][8][4];
#pragma unroll
    for (int i = 0; i < 2; i++)
#pragma unroll
        for (int j = 0; j < 8; j++)
#pragma unroll
            for (int q = 0; q < 4; q++) acc[i][j][q] = 0.f;

    const int nchunk = (K + 31) / 32;
    float4 pa[4], pb[4];

    // prefetch chunk 0  (K % 4 == 0 always here, so k<K implies k+3<K)
    {
        const int k = fqA;   // k0 = 0
#pragma unroll
        for (int i = 0; i < 4; i++) {
            int m = m0 + i * 32 + frA;
            pa[i] = (m < M && k < K) ? *(const float4*)(A + (size_t)m * K + k)
                                     : make_float4(0.f, 0.f, 0.f, 0.f);
        }
#pragma unroll
        for (int i = 0; i < 4; i++) {
            int kk = fkB + 8 * i;
            pb[i] = (kk < K) ? *(const float4*)(W + (size_t)kk * 128 + fnB)
                             : make_float4(0.f, 0.f, 0.f, 0.f);
        }
    }

    for (int c = 0; c < nchunk; c++) {
        __syncthreads();   // previous compute done, smem reusable

        // ---- store+convert prefetched regs into split-bf16 smem
#pragma unroll
        for (int i = 0; i < 4; i++) {
            int r = i * 32 + frA;
            float4 v = pa[i];
            __nv_bfloat162 h01 = __floats2bfloat162_rn(v.x, v.y);
            __nv_bfloat162 h23 = __floats2bfloat162_rn(v.z, v.w);
            float lx = v.x - __bfloat162float(h01.x);
            float ly = v.y - __bfloat162float(h01.y);
            float lz = v.z - __bfloat162float(h23.x);
            float lw = v.w - __bfloat162float(h23.y);
            uint32_t uh01, uh23;
            memcpy(&uh01, &h01, 4); memcpy(&uh23, &h23, 4);
            *(uint2*)&sAh[r * LDT + fqA] = make_uint2(uh01, uh23);
            *(uint2*)&sAl[r * LDT + fqA] = make_uint2(pack2bf(lx, ly), pack2bf(lz, lw));
        }
#pragma unroll
        for (int i = 0; i < 4; i++) {
            int kk = fkB + 8 * i;
            float4 v = pb[i];
            __nv_bfloat162 h01 = __floats2bfloat162_rn(v.x, v.y);
            __nv_bfloat162 h23 = __floats2bfloat162_rn(v.z, v.w);
            float lx = v.x - __bfloat162float(h01.x);
            float ly = v.y - __bfloat162float(h01.y);
            float lz = v.z - __bfloat162float(h23.x);
            float lw = v.w - __bfloat162float(h23.y);
            uint32_t uh01, uh23;
            memcpy(&uh01, &h01, 4); memcpy(&uh23, &h23, 4);
            *(uint2*)&sBh[kk * LDB + fnB] = make_uint2(uh01, uh23);
            *(uint2*)&sBl[kk * LDB + fnB] = make_uint2(pack2bf(lx, ly), pack2bf(lz, lw));
        }
        __syncthreads();

        // ---- prefetch chunk c+1 (LDGs fly during compute below)
        if (c + 1 < nchunk) {
            const int k0n = (c + 1) * 32;
            const int k = k0n + fqA;
#pragma unroll
            for (int i = 0; i < 4; i++) {
                int m = m0 + i * 32 + frA;
                pa[i] = (m < M && k < K) ? *(const float4*)(A + (size_t)m * K + k)
                                         : make_float4(0.f, 0.f, 0.f, 0.f);
            }
#pragma unroll
            for (int i = 0; i < 4; i++) {
                int kk = k0n + fkB + 8 * i;
                pb[i] = (kk < K) ? *(const float4*)(W + (size_t)kk * 128 + fnB)
                                 : make_float4(0.f, 0.f, 0.f, 0.f);
            }
        }

        // ---- compute: 2 k-steps of 16
#pragma unroll
        for (int ks = 0; ks < 2; ks++) {
            const int kb = ks * 16;
            uint32_t ah[2][4], al[2][4];
#pragma unroll
            for (int mt = 0; mt < 2; mt++) {
                uint32_t off = (uint32_t)((wm + mt * 16 + aRow) * LDT + kb + aCol) * 2;
                LDMX4(ah[mt][0], ah[mt][1], ah[mt][2], ah[mt][3], uAh + off);
                LDMX4(al[mt][0], al[mt][1], al[mt][2], al[mt][3], uAl + off);
            }
#pragma unroll
            for (int p = 0; p < 4; p++) {
                uint32_t off = (uint32_t)((kb + bK) * LDB + wn + p * 16 + bN) * 2;
                uint32_t bh[4], bl[4];
                LDMX4T(bh[0], bh[1], bh[2], bh[3], uBh + off);
                LDMX4T(bl[0], bl[1], bl[2], bl[3], uBl + off);
#pragma unroll
                for (int mt = 0; mt < 2; mt++) {
                    MMA16816(acc[mt][2 * p],     ah[mt], bh[0], bh[1]);
                    MMA16816(acc[mt][2 * p],     ah[mt], bl[0], bl[1]);
                    MMA16816(acc[mt][2 * p],     al[mt], bh[0], bh[1]);
                    MMA16816(acc[mt][2 * p + 1], ah[mt], bh[2], bh[3]);
                    MMA16816(acc[mt][2 * p + 1], ah[mt], bl[2], bl[3]);
                    MMA16816(acc[mt][2 * p + 1], al[mt], bh[2], bh[3]);
                }
            }
        }
    }

    // ---- epilogue
    const int fr = lane >> 2, fc = (lane & 3) * 2;
#pragma unroll
    for (int mt = 0; mt < 2; mt++) {
        int r0 = m0 + wm + mt * 16 + fr;
#pragma unroll
        for (int nt = 0; nt < 8; nt++) {
            int cbase = wn + nt * 8 + fc;
            if (r0 < M)
                *(float2*)(C + (size_t)r0 * 128 + cbase) =
                    make_float2(acc[mt][nt][0], acc[mt][nt][1]);
            if (r0 + 8 < M)
                *(float2*)(C + (size_t)(r0 + 8) * 128 + cbase) =
                    make_float2(acc[mt][nt][2], acc[mt][nt][3]);
        }
    }
}

// ---------------- CSR SpMM + bias (+relu) ----------------
// Source rows have FsQ float4s per row; dest rows F/4. Lanes with f>=F idle.
__global__ __launch_bounds__(256) void k_spmm(const float* __restrict__ S,
                                              float* __restrict__ H,
                                              const float* __restrict__ bias,
                                              int F, int FsQ, int do_relu) {
    int wid  = (blockIdx.x * 256 + threadIdx.x) >> 5;
    if (wid >= NN) return;
    int lane = threadIdx.x & 31;
    int f    = lane * 4;
    if (f >= F) return;
    int fq = f >> 2, Fq = F >> 2;

    int beg = g_rp[wid], end = g_rp[wid + 1];
    const float4* Sv = (const float4*)S;
    float4 acc = make_float4(0.f, 0.f, 0.f, 0.f);
    for (int e = beg; e < end; e++) {
        int   c = g_cs[e];
        float w = g_ws[e];
        float4 v = Sv[(size_t)c * FsQ + fq];
        acc.x += w * v.x; acc.y += w * v.y; acc.z += w * v.z; acc.w += w * v.w;
    }
    float4 b = ((const float4*)bias)[fq];
    acc.x += b.x; acc.y += b.y; acc.z += b.z; acc.w += b.w;
    if (do_relu) {
        acc.x = fmaxf(acc.x, 0.f); acc.y = fmaxf(acc.y, 0.f);
        acc.z = fmaxf(acc.z, 0.f); acc.w = fmaxf(acc.w, 0.f);
    }
    ((float4*)H)[(size_t)wid * Fq + fq] = acc;
}

// ---------------- log_softmax over 40 classes ----------------
__global__ __launch_bounds__(256) void k_lsm(float* __restrict__ out) {
    int wid = (blockIdx.x * 256 + threadIdx.x) >> 5;
    if (wid >= NN) return;
    int lane = threadIdx.x & 31;
    const float* a = g_A4 + (size_t)wid * NC;
    float v0 = a[lane];
    float v1 = (lane + 32 < NC) ? a[lane + 32] : -1e30f;
    float m = fmaxf(v0, v1);
#pragma unroll
    for (int o = 16; o; o >>= 1) m = fmaxf(m, __shfl_xor_sync(0xffffffffu, m, o));
    float s = expf(v0 - m) + ((lane + 32 < NC) ? expf(v1 - m) : 0.f);
#pragma unroll
    for (int o = 16; o; o >>= 1) s += __shfl_xor_sync(0xffffffffu, s, o);
    float l = m + logf(s);
    out[(size_t)wid * NC + lane] = v0 - l;
    if (lane + 32 < NC) out[(size_t)wid * NC + lane + 32] = v1 - l;
}

// ---------------- launch ----------------
extern "C" void kernel_launch(void* const* d_in, const int* in_sizes, int n_in,
                              void* d_out, int out_size) {
    const float* x  = (const float*)d_in[0];
    const int*   row = (const int*)d_in[1];
    const int*   col = (const int*)d_in[2];
    const float* ew  = (const float*)d_in[3];
    const float* W1 = (const float*)d_in[4];  const float* b1 = (const float*)d_in[5];
    const float* W2 = (const float*)d_in[6];  const float* b2 = (const float*)d_in[7];
    const float* W3 = (const float*)d_in[8];  const float* b3 = (const float*)d_in[9];
    const float* W4 = (const float*)d_in[10]; const float* b4 = (const float*)d_in[11];
    float* out = (float*)d_out;

    void *pS, *pH, *pH2, *pA4, *pW4p;
    cudaGetSymbolAddress(&pS,   g_S);
    cudaGetSymbolAddress(&pH,   g_H);
    cudaGetSymbolAddress(&pH2,  g_H2);
    cudaGetSymbolAddress(&pA4,  g_A4);
    cudaGetSymbolAddress(&pW4p, g_W4p);
    float* S   = (float*)pS;
    float* H   = (float*)pH;
    float* H2  = (float*)pH2;
    float* A4  = (float*)pA4;
    float* W4p = (float*)pW4p;

    const int EB = (NE + 255) / 256;
    const int GM = (NN + 127) / 128;     // 782 row tiles
    const int SB = (NN + 7) / 8;         // warp-per-row

    // CSR build interleaved with layer-1 GEMM (gemm1 placed at launch index 3
    // so the ncu window lands on it)
    k_zero<<<(NN + 255) / 256, 256>>>();
    k_count<<<EB, 256>>>(row);
    k_scan1<<<NBLK, SCAN_B>>>();
    k_gemm_mma<<<GM, 256>>>(x, W1, S, NN, NF);      // layer-1 support
    k_scan2<<<1, 256>>>();
    k_scan3<<<NBLK, SCAN_B>>>();
    k_scatter<<<EB, 256>>>(row, col, ew);
    k_padw4<<<64, 256>>>(W4);

    // layer 1 aggregate
    k_spmm<<<SB, 256>>>(S, H, b1, NH, NH / 4, 1);
    // layer 2
    k_gemm_mma<<<GM, 256>>>(H, W2, S, NN, NH);
    k_spmm<<<SB, 256>>>(S, H2, b2, NH, NH / 4, 1);
    // layer 3
    k_gemm_mma<<<GM, 256>>>(H2, W3, S, NN, NH);
    k_spmm<<<SB, 256>>>(S, H, b3, NH, NH / 4, 1);
    // layer 4 (padded to 128-wide tensor GEMM) + log_softmax
    k_gemm_mma<<<GM, 256>>>(H, W4p, S, NN, NH);
    k_spmm<<<SB, 256>>>(S, A4, b4, NC, 128 / 4, 0);
    k_lsm<<<SB, 256>>>(out);
}